// round 6
// baseline (speedup 1.0000x reference)
#include <cuda_runtime.h>
#include <cuda_fp16.h>

#define TC 8192
#define TF 131072
#define D_MAX 36.0f
#define NGAUSS 300

__device__ __align__(16) float  g_tabf[TC * 128];       // coarse fp32 W(d) (4 MB)
__device__ __align__(16) uint2  g_tabn[TF * 32];        // fine fp16 nearest table (32 MB)
__device__ __align__(16) float  g_x[4096 * 128];
__device__ __align__(16) float  g_fA[4096 * 128];
__device__ __align__(16) float  g_fB[4096 * 128];
__device__ __align__(16) __half g_fhA[4096 * 128];      // fp16 copies of f for gather
__device__ __align__(16) __half g_fhB[4096 * 128];
__device__ __align__(16) float  g_y[4096 * 128];
__device__ __align__(16) float  g_ysum[4096 * 128];
__device__ __align__(16) float  g_combo[128 * 128];
__device__ __align__(16) float  g_fbias[128];

__device__ __forceinline__ float sspf(float x) {
    return fmaxf(x, 0.0f) + log1pf(__expf(-fabsf(x))) - 0.69314718055994531f;
}

// ---- coarse fp32 table: 512 blocks x 128 thr, 16 rows each ----
__global__ void k_table(const float* __restrict__ w1, const float* __restrict__ b1,
                        const float* __restrict__ w2, const float* __restrict__ b2)
{
    __shared__ float w1s[32 * 128];
    __shared__ float rbf_s[16 * 32];
    __shared__ float As[16 * 128];
    const float hstep = D_MAX / (float)TC;
    const float dc = 30.0f / 299.0f;
    const int t0 = blockIdx.x * 16, h = threadIdx.x;

    float dmin = (float)t0 * hstep, dmax = (float)(t0 + 15) * hstep;
    int glo = (int)floorf((dmin - 1.4f) / dc); if (glo < 0) glo = 0;
    int ghi = (int)ceilf((dmax + 1.4f) / dc);  if (ghi > NGAUSS - 1) ghi = NGAUSS - 1;
    int ng = ghi - glo + 1; if (ng < 0) ng = 0; if (ng > 32) ng = 32;

    for (int idx = h; idx < ng * 128; idx += 128) w1s[idx] = w1[glo * 128 + idx];
    for (int idx = h; idx < 16 * ng; idx += 128) {
        int t = idx / ng, g = idx % ng;
        float d = (float)(t0 + t) * hstep;
        float u = d - (float)(glo + g) * dc;
        rbf_s[t * 32 + g] = __expf(-10.0f * u * u);
    }
    __syncthreads();

    float acc[16];
#pragma unroll
    for (int t = 0; t < 16; t++) acc[t] = 0.0f;
    for (int g = 0; g < ng; g++) {
        float w = w1s[g * 128 + h];
#pragma unroll
        for (int t = 0; t < 16; t++) acc[t] += rbf_s[t * 32 + g] * w;
    }
    float bb = b1[h];
#pragma unroll
    for (int t = 0; t < 16; t++) As[t * 128 + h] = sspf(acc[t] + bb);
    __syncthreads();

#pragma unroll
    for (int t = 0; t < 16; t++) acc[t] = 0.0f;
    for (int k = 0; k < 128; k++) {
        float w = __ldg(&w2[k * 128 + h]);
#pragma unroll
        for (int t = 0; t < 16; t++) acc[t] += As[t * 128 + k] * w;
    }
    float b2v = b2[h];
#pragma unroll
    for (int t = 0; t < 16; t++)
        g_tabf[(t0 + t) * 128 + h] = acc[t] + b2v;
}

// ---- fine table (nearest): entry (t,h4) = W(t*36/TF)[4h4..+3] as 2x half2 ----
__global__ void k_pack()
{
    int g = blockIdx.x * 256 + threadIdx.x;       // over TF*32
    int t = g >> 5, h4 = g & 31;
    int u = t >> 4;
    float fr = (float)(t & 15) * 0.0625f;
    int un = min(u + 1, TC - 1);
    float4 a = *reinterpret_cast<const float4*>(g_tabf + u * 128 + h4 * 4);
    float4 b = *reinterpret_cast<const float4*>(g_tabf + un * 128 + h4 * 4);
    __half2 h01 = __floats2half2_rn(a.x + fr * (b.x - a.x), a.y + fr * (b.y - a.y));
    __half2 h23 = __floats2half2_rn(a.z + fr * (b.z - a.z), a.w + fr * (b.w - a.w));
    uint2 o;
    o.x = *reinterpret_cast<unsigned*>(&h01);
    o.y = *reinterpret_cast<unsigned*>(&h23);
    g_tabn[g] = o;
}

// ---- fused setup: blocks 0-255 = gather+f0, 256-263 = combo, 264 = fbias ----
__global__ void k_setup(const int* __restrict__ z, const float* __restrict__ emb,
                        const float* __restrict__ w_in2f, const float* __restrict__ w_out,
                        const float* __restrict__ b_out)
{
    extern __shared__ float sm[];
    float* ws = sm;            // [128][128]
    float* xs = sm + 16384;    // [16][128]
    const int bx = blockIdx.x, tid = threadIdx.x;

    for (int idx = tid; idx < 16384; idx += 256) ws[idx] = w_in2f[idx];
    if (bx < 256) {
        int r0 = bx * 16;
        for (int idx = tid; idx < 2048; idx += 256) {
            int i = idx >> 7, h = idx & 127;
            int zi = z[r0 + i];
            float v = emb[zi * 128 + h];
            xs[idx] = v;
            g_x[r0 * 128 + idx] = v;
            g_ysum[r0 * 128 + idx] = 0.0f;
        }
    } else if (bx < 264) {
        int r0 = (bx - 256) * 16;
        for (int idx = tid; idx < 2048; idx += 256) xs[idx] = w_out[r0 * 128 + idx];
    }
    __syncthreads();

    if (bx == 264) {
        if (tid < 128) {
            float s = 0.0f;
            for (int m = 0; m < 128; m++) s += __ldg(&b_out[m]) * ws[m * 128 + tid];
            g_fbias[tid] = s;
        }
        return;
    }
    const int rg = tid >> 5, hg = tid & 31;
    float a[2][4];
#pragma unroll
    for (int rr = 0; rr < 2; rr++)
#pragma unroll
        for (int c = 0; c < 4; c++) a[rr][c] = 0.0f;
    for (int k = 0; k < 128; k++) {
        float4 wb = *reinterpret_cast<const float4*>(ws + k * 128 + hg * 4);
        float y0 = xs[(rg * 2) * 128 + k], y1 = xs[(rg * 2 + 1) * 128 + k];
        a[0][0] += y0 * wb.x; a[0][1] += y0 * wb.y; a[0][2] += y0 * wb.z; a[0][3] += y0 * wb.w;
        a[1][0] += y1 * wb.x; a[1][1] += y1 * wb.y; a[1][2] += y1 * wb.z; a[1][3] += y1 * wb.w;
    }
    if (bx < 256) {
#pragma unroll
        for (int rr = 0; rr < 2; rr++) {
            int row = bx * 16 + rg * 2 + rr;
            *reinterpret_cast<float4*>(g_fA + row * 128 + hg * 4) =
                make_float4(a[rr][0], a[rr][1], a[rr][2], a[rr][3]);
            __half2 h01 = __floats2half2_rn(a[rr][0], a[rr][1]);
            __half2 h23 = __floats2half2_rn(a[rr][2], a[rr][3]);
            uint2 hv;
            hv.x = *reinterpret_cast<unsigned*>(&h01);
            hv.y = *reinterpret_cast<unsigned*>(&h23);
            *reinterpret_cast<uint2*>(g_fhA + row * 128 + hg * 4) = hv;
        }
    } else {
#pragma unroll
        for (int rr = 0; rr < 2; rr++)
            *reinterpret_cast<float4*>(g_combo + ((bx - 256) * 16 + rg * 2 + rr) * 128 + hg * 4) =
                make_float4(a[rr][0], a[rr][1], a[rr][2], a[rr][3]);
    }
}

// ---- gather: y[i,h] = sum_j Wtab[idx(i,j)][h] * f[j,h]. grid (16,32) x 256 ----
__global__ void __launch_bounds__(256) k_gather(const float* __restrict__ r, int flag)
{
    __shared__ __align__(16) __half f_s[128 * 128];   // 32 KB
    __shared__ unsigned idx_s[8 * 128];               // 4 KB
    __shared__ float rs[384];
    const int it = blockIdx.x, b = blockIdx.y, tid = threadIdx.x;
    const __half* fh = (flag ? g_fhB : g_fhA) + b * 16384;
    const float inv_h = (float)TF / D_MAX;

    if (tid < 128) {
        const float* rp = r + (b * 128 + tid) * 3;
        rs[tid] = rp[0]; rs[128 + tid] = rp[1]; rs[256 + tid] = rp[2];
    }
    for (int idx = tid; idx < 2048; idx += 256)
        reinterpret_cast<uint4*>(f_s)[idx] = reinterpret_cast<const uint4*>(fh)[idx];
    __syncthreads();
    for (int task = tid; task < 1024; task += 256) {
        int il = task >> 7, j = task & 127;
        int ig = it * 8 + il;
        float dx = rs[ig] - rs[j], dy = rs[128 + ig] - rs[128 + j], dz = rs[256 + ig] - rs[256 + j];
        float d = sqrtf(dx * dx + dy * dy + dz * dz + 1e-12f);
        float t = fminf(d * inv_h + 0.5f, (float)(TF - 1));
        idx_s[task] = (unsigned)t;
    }
    __syncthreads();

    const int w = tid >> 5, lane = tid & 31;
    const unsigned* ip = idx_s + w * 128;
    float a0 = 0.f, a1 = 0.f, a2 = 0.f, a3 = 0.f;
#pragma unroll 8
    for (int j = 0; j < 128; j++) {
        unsigned t = ip[j];
        uint2 u = g_tabn[(size_t)t * 32 + lane];
        uint2 fv = *reinterpret_cast<const uint2*>(f_s + j * 128 + lane * 4);
        __half2 w01 = *reinterpret_cast<__half2*>(&u.x);
        __half2 w23 = *reinterpret_cast<__half2*>(&u.y);
        __half2 f01 = *reinterpret_cast<__half2*>(&fv.x);
        __half2 f23 = *reinterpret_cast<__half2*>(&fv.y);
        float2 pw0 = __half22float2(w01), pw1 = __half22float2(w23);
        float2 pf0 = __half22float2(f01), pf1 = __half22float2(f23);
        a0 = fmaf(pw0.x, pf0.x, a0);
        a1 = fmaf(pw0.y, pf0.y, a1);
        a2 = fmaf(pw1.x, pf1.x, a2);
        a3 = fmaf(pw1.y, pf1.y, a3);
    }
    int i = it * 8 + w;
    *reinterpret_cast<float4*>(g_y + (b * 128 + i) * 128 + lane * 4) =
        make_float4(a0, a1, a2, a3);
}

// ---- epilogue: y2 = ssp(y@w_f2out+b); ysum += y2; f_out = f_in + fbias + y2@combo ----
__global__ void __launch_bounds__(256) k_epi(const float* __restrict__ w_f2out,
                                             const float* __restrict__ b_f2out, int flag)
{
    extern __shared__ float sm[];
    float* buf  = sm;            // 64 KB weights
    float* y_s  = sm + 16384;    // 8 KB
    float* y2_s = y_s + 2048;    // 8 KB
    const int r0 = blockIdx.x * 16, tid = threadIdx.x;
    const float* f_in  = flag ? g_fB : g_fA;
    float*       f_out = flag ? g_fA : g_fB;
    __half*      fh_out = flag ? g_fhA : g_fhB;

    for (int idx = tid; idx < 16384; idx += 256) buf[idx] = w_f2out[idx];
    for (int idx = tid; idx < 2048; idx += 256) y_s[idx] = g_y[r0 * 128 + idx];
    __syncthreads();

    const int rg = tid >> 5, hg = tid & 31;
    float a[2][4];
#pragma unroll
    for (int rr = 0; rr < 2; rr++)
#pragma unroll
        for (int c = 0; c < 4; c++) a[rr][c] = 0.0f;
    for (int k = 0; k < 128; k++) {
        float4 wb = *reinterpret_cast<const float4*>(buf + k * 128 + hg * 4);
        float y0 = y_s[(rg * 2) * 128 + k], y1 = y_s[(rg * 2 + 1) * 128 + k];
        a[0][0] += y0 * wb.x; a[0][1] += y0 * wb.y; a[0][2] += y0 * wb.z; a[0][3] += y0 * wb.w;
        a[1][0] += y1 * wb.x; a[1][1] += y1 * wb.y; a[1][2] += y1 * wb.z; a[1][3] += y1 * wb.w;
    }
    {
        float4 bb = *reinterpret_cast<const float4*>(b_f2out + hg * 4);
#pragma unroll
        for (int rr = 0; rr < 2; rr++)
            *reinterpret_cast<float4*>(y2_s + (rg * 2 + rr) * 128 + hg * 4) =
                make_float4(sspf(a[rr][0] + bb.x), sspf(a[rr][1] + bb.y),
                            sspf(a[rr][2] + bb.z), sspf(a[rr][3] + bb.w));
    }
    __syncthreads();
#pragma unroll
    for (int k = 0; k < 8; k++) {
        int idx = tid + k * 256;
        int i = idx >> 7, h = idx & 127;
        g_ysum[(r0 + i) * 128 + h] += y2_s[i * 128 + h];
    }
    for (int idx = tid; idx < 16384; idx += 256) buf[idx] = g_combo[idx];
    __syncthreads();
#pragma unroll
    for (int rr = 0; rr < 2; rr++)
#pragma unroll
        for (int c = 0; c < 4; c++) a[rr][c] = 0.0f;
    for (int k = 0; k < 128; k++) {
        float4 wb = *reinterpret_cast<const float4*>(buf + k * 128 + hg * 4);
        float y0 = y2_s[(rg * 2) * 128 + k], y1 = y2_s[(rg * 2 + 1) * 128 + k];
        a[0][0] += y0 * wb.x; a[0][1] += y0 * wb.y; a[0][2] += y0 * wb.z; a[0][3] += y0 * wb.w;
        a[1][0] += y1 * wb.x; a[1][1] += y1 * wb.y; a[1][2] += y1 * wb.z; a[1][3] += y1 * wb.w;
    }
    {
        float4 fb = *reinterpret_cast<const float4*>(g_fbias + hg * 4);
#pragma unroll
        for (int rr = 0; rr < 2; rr++) {
            int grow = (r0 + rg * 2 + rr) * 128 + hg * 4;
            float4 fo = *reinterpret_cast<const float4*>(f_in + grow);
            float4 o = make_float4(fo.x + fb.x + a[rr][0], fo.y + fb.y + a[rr][1],
                                   fo.z + fb.z + a[rr][2], fo.w + fb.w + a[rr][3]);
            *reinterpret_cast<float4*>(f_out + grow) = o;
            __half2 h01 = __floats2half2_rn(o.x, o.y);
            __half2 h23 = __floats2half2_rn(o.z, o.w);
            uint2 hv;
            hv.x = *reinterpret_cast<unsigned*>(&h01);
            hv.y = *reinterpret_cast<unsigned*>(&h23);
            *reinterpret_cast<uint2*>(fh_out + grow) = hv;
        }
    }
}

// ---- readout ----
__global__ void k_ro(const float* __restrict__ w_out, const float* __restrict__ b_out,
                     const float* __restrict__ w1, const float* __restrict__ b1,
                     const float* __restrict__ w2, const float* __restrict__ b2,
                     float* __restrict__ out)
{
    extern __shared__ char smb[];
    float* buf = (float*)smb;                   // 64 KB weights
    float* sy  = (float*)(smb + 65536);         // 8 KB: ysum rows -> yro
    float* xf  = sy + 2048;                     // 8 KB
    float* w2s = xf + 2048;                     // 128
    float* part = w2s + 128;                    // 256
    const int r0 = blockIdx.x * 16, tid = threadIdx.x;

    for (int idx = tid; idx < 16384; idx += 256) buf[idx] = w_out[idx];
    for (int idx = tid; idx < 2048; idx += 256) sy[idx] = g_ysum[r0 * 128 + idx];
    if (tid < 128) w2s[tid] = w2[tid];
    __syncthreads();
    const int rg = tid >> 5, hg = tid & 31;
    float a[2][4];
#pragma unroll
    for (int rr = 0; rr < 2; rr++)
#pragma unroll
        for (int c = 0; c < 4; c++) a[rr][c] = 0.0f;
    for (int k = 0; k < 128; k++) {
        float4 wb = *reinterpret_cast<const float4*>(buf + k * 128 + hg * 4);
        float y0 = sy[(rg * 2) * 128 + k], y1 = sy[(rg * 2 + 1) * 128 + k];
        a[0][0] += y0 * wb.x; a[0][1] += y0 * wb.y; a[0][2] += y0 * wb.z; a[0][3] += y0 * wb.w;
        a[1][0] += y1 * wb.x; a[1][1] += y1 * wb.y; a[1][2] += y1 * wb.z; a[1][3] += y1 * wb.w;
    }
    {
        float4 bb = *reinterpret_cast<const float4*>(b_out + hg * 4);
#pragma unroll
        for (int rr = 0; rr < 2; rr++) {
            int grow = (r0 + rg * 2 + rr) * 128 + hg * 4;
            float4 x0 = *reinterpret_cast<const float4*>(g_x + grow);
            *reinterpret_cast<float4*>(xf + (rg * 2 + rr) * 128 + hg * 4) =
                make_float4(x0.x + a[rr][0] + 3.0f * bb.x, x0.y + a[rr][1] + 3.0f * bb.y,
                            x0.z + a[rr][2] + 3.0f * bb.z, x0.w + a[rr][3] + 3.0f * bb.w);
        }
    }
    __syncthreads();
    for (int idx = tid; idx < 16384; idx += 256) buf[idx] = w1[idx];
    __syncthreads();
#pragma unroll
    for (int rr = 0; rr < 2; rr++)
#pragma unroll
        for (int c = 0; c < 4; c++) a[rr][c] = 0.0f;
    for (int k = 0; k < 128; k++) {
        float4 wb = *reinterpret_cast<const float4*>(buf + k * 128 + hg * 4);
        float y0 = xf[(rg * 2) * 128 + k], y1 = xf[(rg * 2 + 1) * 128 + k];
        a[0][0] += y0 * wb.x; a[0][1] += y0 * wb.y; a[0][2] += y0 * wb.z; a[0][3] += y0 * wb.w;
        a[1][0] += y1 * wb.x; a[1][1] += y1 * wb.y; a[1][2] += y1 * wb.z; a[1][3] += y1 * wb.w;
    }
    __syncthreads();
    {
        float4 bb = *reinterpret_cast<const float4*>(b1 + hg * 4);
#pragma unroll
        for (int rr = 0; rr < 2; rr++)
            *reinterpret_cast<float4*>(sy + (rg * 2 + rr) * 128 + hg * 4) =
                make_float4(sspf(a[rr][0] + bb.x), sspf(a[rr][1] + bb.y),
                            sspf(a[rr][2] + bb.z), sspf(a[rr][3] + bb.w));
    }
    __syncthreads();
    {
        int row = tid >> 4, seg = tid & 15;
        float s = 0.0f;
#pragma unroll
        for (int t = 0; t < 8; t++)
            s += sy[row * 128 + seg * 8 + t] * w2s[seg * 8 + t];
        part[tid] = s;
    }
    __syncthreads();
    if (tid < 16) {
        float s = 0.0f;
#pragma unroll
        for (int q = 0; q < 16; q++) s += part[tid * 16 + q];
        out[r0 + tid] = s + b2[0];
    }
}

extern "C" void kernel_launch(void* const* d_in, const int* in_sizes, int n_in,
                              void* d_out, int out_size)
{
    const int*   z       = (const int*)  d_in[0];
    const float* r       = (const float*)d_in[1];
    const float* emb     = (const float*)d_in[2];
    const float* w_in2f  = (const float*)d_in[3];
    const float* w_f1    = (const float*)d_in[4];
    const float* b_f1    = (const float*)d_in[5];
    const float* w_f2    = (const float*)d_in[6];
    const float* b_f2    = (const float*)d_in[7];
    const float* w_f2out = (const float*)d_in[8];
    const float* b_f2out = (const float*)d_in[9];
    const float* w_out   = (const float*)d_in[10];
    const float* b_out   = (const float*)d_in[11];
    const float* w_aw1   = (const float*)d_in[12];
    const float* b_aw1   = (const float*)d_in[13];
    const float* w_aw2   = (const float*)d_in[14];
    const float* b_aw2   = (const float*)d_in[15];
    float* out = (float*)d_out;

    cudaFuncSetAttribute(k_setup, cudaFuncAttributeMaxDynamicSharedMemorySize, 73728);
    cudaFuncSetAttribute(k_epi,   cudaFuncAttributeMaxDynamicSharedMemorySize, 81920);
    cudaFuncSetAttribute(k_ro,    cudaFuncAttributeMaxDynamicSharedMemorySize, 86016);

    k_table<<<512, 128>>>(w_f1, b_f1, w_f2, b_f2);
    k_pack<<<16384, 256>>>();
    k_setup<<<265, 256, 73728>>>(z, emb, w_in2f, w_out, b_out);
    for (int it = 0; it < 3; it++) {
        k_gather<<<dim3(16, 32), 256>>>(r, it & 1);
        k_epi<<<256, 256, 81920>>>(w_f2out, b_f2out, it & 1);
    }
    k_ro<<<256, 256, 86016>>>(w_out, b_out, w_aw1, b_aw1, w_aw2, b_aw2, out);
}

// round 7
// speedup vs baseline: 1.2942x; 1.2942x over previous
#include <cuda_runtime.h>
#include <cuda_fp16.h>

#define TC 8192
#define TF 131072
#define D_MAX 36.0f
#define NGAUSS 300

__device__ __align__(16) float  g_tabf[TC * 128];       // coarse fp32 W(d) (4 MB)
__device__ __align__(16) uint2  g_tabn[TF * 32];        // fine fp16 nearest table (32 MB)
__device__ __align__(16) float  g_x[4096 * 128];
__device__ __align__(16) float  g_fA[4096 * 128];
__device__ __align__(16) float  g_fB[4096 * 128];
__device__ __align__(16) __half g_fhA[4096 * 128];      // fp16 copies of f for gather
__device__ __align__(16) __half g_fhB[4096 * 128];
__device__ __align__(16) float  g_ysum[4096 * 128];
__device__ __align__(16) float  g_combo[128 * 128];
__device__ __align__(16) float  g_fbias[128];
__device__ __align__(16) __half g_wf2hT[128 * 128];     // w_f2out^T fp16 [n][k]
__device__ __align__(16) __half g_comboT[128 * 128];    // combo^T fp16 [n][k]

__device__ __forceinline__ float sspf(float x) {
    return fmaxf(x, 0.0f) + log1pf(__expf(-fabsf(x))) - 0.69314718055994531f;
}

__device__ __forceinline__ void mma16816(float& d0, float& d1, float& d2, float& d3,
                                         unsigned a0, unsigned a1, unsigned a2, unsigned a3,
                                         unsigned b0, unsigned b1)
{
    asm volatile(
        "mma.sync.aligned.m16n8k16.row.col.f32.f16.f16.f32 "
        "{%0,%1,%2,%3}, {%4,%5,%6,%7}, {%8,%9}, {%0,%1,%2,%3};\n"
        : "+f"(d0), "+f"(d1), "+f"(d2), "+f"(d3)
        : "r"(a0), "r"(a1), "r"(a2), "r"(a3), "r"(b0), "r"(b1));
}

// ---- coarse fp32 table: 512 blocks x 128 thr, 16 rows each ----
__global__ void k_table(const float* __restrict__ w1, const float* __restrict__ b1,
                        const float* __restrict__ w2, const float* __restrict__ b2)
{
    __shared__ float w1s[32 * 128];
    __shared__ float rbf_s[16 * 32];
    __shared__ float As[16 * 128];
    const float hstep = D_MAX / (float)TC;
    const float dc = 30.0f / 299.0f;
    const int t0 = blockIdx.x * 16, h = threadIdx.x;

    float dmin = (float)t0 * hstep, dmax = (float)(t0 + 15) * hstep;
    int glo = (int)floorf((dmin - 1.4f) / dc); if (glo < 0) glo = 0;
    int ghi = (int)ceilf((dmax + 1.4f) / dc);  if (ghi > NGAUSS - 1) ghi = NGAUSS - 1;
    int ng = ghi - glo + 1; if (ng < 0) ng = 0; if (ng > 32) ng = 32;

    for (int idx = h; idx < ng * 128; idx += 128) w1s[idx] = w1[glo * 128 + idx];
    for (int idx = h; idx < 16 * ng; idx += 128) {
        int t = idx / ng, g = idx % ng;
        float d = (float)(t0 + t) * hstep;
        float u = d - (float)(glo + g) * dc;
        rbf_s[t * 32 + g] = __expf(-10.0f * u * u);
    }
    __syncthreads();

    float acc[16];
#pragma unroll
    for (int t = 0; t < 16; t++) acc[t] = 0.0f;
    for (int g = 0; g < ng; g++) {
        float w = w1s[g * 128 + h];
#pragma unroll
        for (int t = 0; t < 16; t++) acc[t] += rbf_s[t * 32 + g] * w;
    }
    float bb = b1[h];
#pragma unroll
    for (int t = 0; t < 16; t++) As[t * 128 + h] = sspf(acc[t] + bb);
    __syncthreads();

#pragma unroll
    for (int t = 0; t < 16; t++) acc[t] = 0.0f;
    for (int k = 0; k < 128; k++) {
        float w = __ldg(&w2[k * 128 + h]);
#pragma unroll
        for (int t = 0; t < 16; t++) acc[t] += As[t * 128 + k] * w;
    }
    float b2v = b2[h];
#pragma unroll
    for (int t = 0; t < 16; t++)
        g_tabf[(t0 + t) * 128 + h] = acc[t] + b2v;
}

// ---- fine table (nearest) ----
__global__ void k_pack()
{
    int g = blockIdx.x * 256 + threadIdx.x;       // over TF*32
    int t = g >> 5, h4 = g & 31;
    int u = t >> 4;
    float fr = (float)(t & 15) * 0.0625f;
    int un = min(u + 1, TC - 1);
    float4 a = *reinterpret_cast<const float4*>(g_tabf + u * 128 + h4 * 4);
    float4 b = *reinterpret_cast<const float4*>(g_tabf + un * 128 + h4 * 4);
    __half2 h01 = __floats2half2_rn(a.x + fr * (b.x - a.x), a.y + fr * (b.y - a.y));
    __half2 h23 = __floats2half2_rn(a.z + fr * (b.z - a.z), a.w + fr * (b.w - a.w));
    uint2 o;
    o.x = *reinterpret_cast<unsigned*>(&h01);
    o.y = *reinterpret_cast<unsigned*>(&h23);
    g_tabn[g] = o;
}

// ---- fused setup: blocks 0-255 = gather+f0, 256-263 = combo, 264 = fbias ----
__global__ void k_setup(const int* __restrict__ z, const float* __restrict__ emb,
                        const float* __restrict__ w_in2f, const float* __restrict__ w_out,
                        const float* __restrict__ b_out)
{
    extern __shared__ float sm[];
    float* ws = sm;            // [128][128]
    float* xs = sm + 16384;    // [16][128]
    const int bx = blockIdx.x, tid = threadIdx.x;

    for (int idx = tid; idx < 16384; idx += 256) ws[idx] = w_in2f[idx];
    if (bx < 256) {
        int r0 = bx * 16;
        for (int idx = tid; idx < 2048; idx += 256) {
            int i = idx >> 7, h = idx & 127;
            int zi = z[r0 + i];
            float v = emb[zi * 128 + h];
            xs[idx] = v;
            g_x[r0 * 128 + idx] = v;
            g_ysum[r0 * 128 + idx] = 0.0f;
        }
    } else if (bx < 264) {
        int r0 = (bx - 256) * 16;
        for (int idx = tid; idx < 2048; idx += 256) xs[idx] = w_out[r0 * 128 + idx];
    }
    __syncthreads();

    if (bx == 264) {
        if (tid < 128) {
            float s = 0.0f;
            for (int m = 0; m < 128; m++) s += __ldg(&b_out[m]) * ws[m * 128 + tid];
            g_fbias[tid] = s;
        }
        return;
    }
    const int rg = tid >> 5, hg = tid & 31;
    float a[2][4];
#pragma unroll
    for (int rr = 0; rr < 2; rr++)
#pragma unroll
        for (int c = 0; c < 4; c++) a[rr][c] = 0.0f;
    for (int k = 0; k < 128; k++) {
        float4 wb = *reinterpret_cast<const float4*>(ws + k * 128 + hg * 4);
        float y0 = xs[(rg * 2) * 128 + k], y1 = xs[(rg * 2 + 1) * 128 + k];
        a[0][0] += y0 * wb.x; a[0][1] += y0 * wb.y; a[0][2] += y0 * wb.z; a[0][3] += y0 * wb.w;
        a[1][0] += y1 * wb.x; a[1][1] += y1 * wb.y; a[1][2] += y1 * wb.z; a[1][3] += y1 * wb.w;
    }
    if (bx < 256) {
#pragma unroll
        for (int rr = 0; rr < 2; rr++) {
            int row = bx * 16 + rg * 2 + rr;
            *reinterpret_cast<float4*>(g_fA + row * 128 + hg * 4) =
                make_float4(a[rr][0], a[rr][1], a[rr][2], a[rr][3]);
            __half2 h01 = __floats2half2_rn(a[rr][0], a[rr][1]);
            __half2 h23 = __floats2half2_rn(a[rr][2], a[rr][3]);
            uint2 hv;
            hv.x = *reinterpret_cast<unsigned*>(&h01);
            hv.y = *reinterpret_cast<unsigned*>(&h23);
            *reinterpret_cast<uint2*>(g_fhA + row * 128 + hg * 4) = hv;
        }
    } else {
#pragma unroll
        for (int rr = 0; rr < 2; rr++)
            *reinterpret_cast<float4*>(g_combo + ((bx - 256) * 16 + rg * 2 + rr) * 128 + hg * 4) =
                make_float4(a[rr][0], a[rr][1], a[rr][2], a[rr][3]);
    }
}

// ---- transposed fp16 weight copies: 64 blocks x 256 ----
__global__ void k_prep(const float* __restrict__ w_f2out)
{
    int idx = blockIdx.x * 256 + threadIdx.x;   // dst idx = n*128 + k
    int n = idx >> 7, k = idx & 127;
    g_wf2hT[idx] = __float2half(w_f2out[k * 128 + n]);
    g_comboT[idx] = __float2half(g_combo[k * 128 + n]);
}

// ---- fused iteration: gather + mma epilogue. grid (8, 32) x 512 thr ----
// block = 16 i-rows; warp w gathers row w; then 16 warps do m16n8 mma tiles.
#define YH_STRIDE 136
__global__ void __launch_bounds__(512) k_iter(const float* __restrict__ r,
                                              const float* __restrict__ b_f2out, int flag)
{
    extern __shared__ char smb[];
    __half*   f_s   = (__half*)smb;                  // 32 KB [j][h]
    __half*   yh    = (__half*)(smb + 32768);        // 16 x 136 fp16
    __half*   y2h   = (__half*)(smb + 37248);        // 16 x 136 fp16
    unsigned* idx_s = (unsigned*)(smb + 41728);      // 16 x 128
    float*    rs    = (float*)(smb + 49920);         // 384 f
    float*    bias1 = (float*)(smb + 51456);         // 128 f
    float*    fb_s  = (float*)(smb + 51968);         // 128 f
    const int it = blockIdx.x, b = blockIdx.y, tid = threadIdx.x;
    const __half* fh_in = (flag ? g_fhB : g_fhA) + b * 16384;
    const float*  f_in  = flag ? g_fB : g_fA;
    float*        f_out = flag ? g_fA : g_fB;
    __half*       fh_out = flag ? g_fhA : g_fhB;
    const float inv_h = (float)TF / D_MAX;

    if (tid < 128) {
        const float* rp = r + (b * 128 + tid) * 3;
        rs[tid] = rp[0]; rs[128 + tid] = rp[1]; rs[256 + tid] = rp[2];
    } else if (tid < 256) {
        bias1[tid - 128] = b_f2out[tid - 128];
    } else if (tid < 384) {
        fb_s[tid - 256] = g_fbias[tid - 256];
    }
    for (int i2 = tid; i2 < 2048; i2 += 512)
        reinterpret_cast<uint4*>(f_s)[i2] = reinterpret_cast<const uint4*>(fh_in)[i2];
    __syncthreads();
    for (int task = tid; task < 2048; task += 512) {
        int il = task >> 7, j = task & 127;
        int ig = it * 16 + il;
        float dx = rs[ig] - rs[j], dy = rs[128 + ig] - rs[128 + j], dz = rs[256 + ig] - rs[256 + j];
        float d = sqrtf(dx * dx + dy * dy + dz * dz + 1e-12f);
        idx_s[task] = (unsigned)fminf(d * inv_h + 0.5f, (float)(TF - 1));
    }
    __syncthreads();

    const int w = tid >> 5, lane = tid & 31;
    {
        const unsigned* ip = idx_s + w * 128;
        float a0 = 0.f, a1 = 0.f, a2 = 0.f, a3 = 0.f;
#pragma unroll 8
        for (int j = 0; j < 128; j++) {
            unsigned t = ip[j];
            uint2 u = g_tabn[(size_t)t * 32 + lane];
            uint2 fv = *reinterpret_cast<const uint2*>(f_s + j * 128 + lane * 4);
            __half2 w01 = *reinterpret_cast<__half2*>(&u.x);
            __half2 w23 = *reinterpret_cast<__half2*>(&u.y);
            __half2 f01 = *reinterpret_cast<__half2*>(&fv.x);
            __half2 f23 = *reinterpret_cast<__half2*>(&fv.y);
            float2 pw0 = __half22float2(w01), pw1 = __half22float2(w23);
            float2 pf0 = __half22float2(f01), pf1 = __half22float2(f23);
            a0 = fmaf(pw0.x, pf0.x, a0);
            a1 = fmaf(pw0.y, pf0.y, a1);
            a2 = fmaf(pw1.x, pf1.x, a2);
            a3 = fmaf(pw1.y, pf1.y, a3);
        }
        __half2 h01 = __floats2half2_rn(a0, a1);
        __half2 h23 = __floats2half2_rn(a2, a3);
        uint2 hv;
        hv.x = *reinterpret_cast<unsigned*>(&h01);
        hv.y = *reinterpret_cast<unsigned*>(&h23);
        *reinterpret_cast<uint2*>(yh + w * YH_STRIDE + lane * 4) = hv;
    }
    __syncthreads();

    // ---- GEMM1 (mma): y2 = ssp(y @ w_f2out + b); ysum += y2 ----
    const int gr = lane >> 2, ct = lane & 3, n0 = w * 8;
    const int nc = n0 + gr;             // B n-index for this lane
    const int c0 = n0 + ct * 2;         // D col for this lane
    float d0 = 0.f, d1 = 0.f, d2 = 0.f, d3 = 0.f;
#pragma unroll
    for (int ks = 0; ks < 8; ks++) {
        int kb = ks * 16 + ct * 2;
        unsigned A0 = *reinterpret_cast<const unsigned*>(yh + gr * YH_STRIDE + kb);
        unsigned A1 = *reinterpret_cast<const unsigned*>(yh + (gr + 8) * YH_STRIDE + kb);
        unsigned A2 = *reinterpret_cast<const unsigned*>(yh + gr * YH_STRIDE + kb + 8);
        unsigned A3 = *reinterpret_cast<const unsigned*>(yh + (gr + 8) * YH_STRIDE + kb + 8);
        unsigned B0 = *reinterpret_cast<const unsigned*>(g_wf2hT + nc * 128 + kb);
        unsigned B1 = *reinterpret_cast<const unsigned*>(g_wf2hT + nc * 128 + kb + 8);
        mma16816(d0, d1, d2, d3, A0, A1, A2, A3, B0, B1);
    }
    {
        float v0 = sspf(d0 + bias1[c0]), v1 = sspf(d1 + bias1[c0 + 1]);
        float v2 = sspf(d2 + bias1[c0]), v3 = sspf(d3 + bias1[c0 + 1]);
        int gr0 = (b * 128 + it * 16 + gr) * 128 + c0;
        int gr1 = gr0 + 8 * 128;
        float2 s0 = *reinterpret_cast<float2*>(g_ysum + gr0);
        float2 s1 = *reinterpret_cast<float2*>(g_ysum + gr1);
        s0.x += v0; s0.y += v1; s1.x += v2; s1.y += v3;
        *reinterpret_cast<float2*>(g_ysum + gr0) = s0;
        *reinterpret_cast<float2*>(g_ysum + gr1) = s1;
        __half2 p01 = __floats2half2_rn(v0, v1);
        __half2 p23 = __floats2half2_rn(v2, v3);
        *reinterpret_cast<unsigned*>(y2h + gr * YH_STRIDE + c0) =
            *reinterpret_cast<unsigned*>(&p01);
        *reinterpret_cast<unsigned*>(y2h + (gr + 8) * YH_STRIDE + c0) =
            *reinterpret_cast<unsigned*>(&p23);
    }
    __syncthreads();

    // ---- GEMM2 (mma): f_out = f_in + fbias + y2 @ combo ----
    d0 = d1 = d2 = d3 = 0.f;
#pragma unroll
    for (int ks = 0; ks < 8; ks++) {
        int kb = ks * 16 + ct * 2;
        unsigned A0 = *reinterpret_cast<const unsigned*>(y2h + gr * YH_STRIDE + kb);
        unsigned A1 = *reinterpret_cast<const unsigned*>(y2h + (gr + 8) * YH_STRIDE + kb);
        unsigned A2 = *reinterpret_cast<const unsigned*>(y2h + gr * YH_STRIDE + kb + 8);
        unsigned A3 = *reinterpret_cast<const unsigned*>(y2h + (gr + 8) * YH_STRIDE + kb + 8);
        unsigned B0 = *reinterpret_cast<const unsigned*>(g_comboT + nc * 128 + kb);
        unsigned B1 = *reinterpret_cast<const unsigned*>(g_comboT + nc * 128 + kb + 8);
        mma16816(d0, d1, d2, d3, A0, A1, A2, A3, B0, B1);
    }
    {
        int gr0 = (b * 128 + it * 16 + gr) * 128 + c0;
        int gr1 = gr0 + 8 * 128;
        float2 fi0 = *reinterpret_cast<const float2*>(f_in + gr0);
        float2 fi1 = *reinterpret_cast<const float2*>(f_in + gr1);
        float fb0 = fb_s[c0], fb1 = fb_s[c0 + 1];
        float o0 = fi0.x + fb0 + d0, o1 = fi0.y + fb1 + d1;
        float o2 = fi1.x + fb0 + d2, o3 = fi1.y + fb1 + d3;
        *reinterpret_cast<float2*>(f_out + gr0) = make_float2(o0, o1);
        *reinterpret_cast<float2*>(f_out + gr1) = make_float2(o2, o3);
        __half2 q01 = __floats2half2_rn(o0, o1);
        __half2 q23 = __floats2half2_rn(o2, o3);
        *reinterpret_cast<unsigned*>(fh_out + gr0) = *reinterpret_cast<unsigned*>(&q01);
        *reinterpret_cast<unsigned*>(fh_out + gr1) = *reinterpret_cast<unsigned*>(&q23);
    }
}

// ---- readout ----
__global__ void k_ro(const float* __restrict__ w_out, const float* __restrict__ b_out,
                     const float* __restrict__ w1, const float* __restrict__ b1,
                     const float* __restrict__ w2, const float* __restrict__ b2,
                     float* __restrict__ out)
{
    extern __shared__ char smb[];
    float* buf = (float*)smb;                   // 64 KB weights
    float* sy  = (float*)(smb + 65536);         // 8 KB: ysum rows -> yro
    float* xf  = sy + 2048;                     // 8 KB
    float* w2s = xf + 2048;                     // 128
    float* part = w2s + 128;                    // 256
    const int r0 = blockIdx.x * 16, tid = threadIdx.x;

    for (int idx = tid; idx < 16384; idx += 256) buf[idx] = w_out[idx];
    for (int idx = tid; idx < 2048; idx += 256) sy[idx] = g_ysum[r0 * 128 + idx];
    if (tid < 128) w2s[tid] = w2[tid];
    __syncthreads();
    const int rg = tid >> 5, hg = tid & 31;
    float a[2][4];
#pragma unroll
    for (int rr = 0; rr < 2; rr++)
#pragma unroll
        for (int c = 0; c < 4; c++) a[rr][c] = 0.0f;
    for (int k = 0; k < 128; k++) {
        float4 wb = *reinterpret_cast<const float4*>(buf + k * 128 + hg * 4);
        float y0 = sy[(rg * 2) * 128 + k], y1 = sy[(rg * 2 + 1) * 128 + k];
        a[0][0] += y0 * wb.x; a[0][1] += y0 * wb.y; a[0][2] += y0 * wb.z; a[0][3] += y0 * wb.w;
        a[1][0] += y1 * wb.x; a[1][1] += y1 * wb.y; a[1][2] += y1 * wb.z; a[1][3] += y1 * wb.w;
    }
    {
        float4 bb = *reinterpret_cast<const float4*>(b_out + hg * 4);
#pragma unroll
        for (int rr = 0; rr < 2; rr++) {
            int grow = (r0 + rg * 2 + rr) * 128 + hg * 4;
            float4 x0 = *reinterpret_cast<const float4*>(g_x + grow);
            *reinterpret_cast<float4*>(xf + (rg * 2 + rr) * 128 + hg * 4) =
                make_float4(x0.x + a[rr][0] + 3.0f * bb.x, x0.y + a[rr][1] + 3.0f * bb.y,
                            x0.z + a[rr][2] + 3.0f * bb.z, x0.w + a[rr][3] + 3.0f * bb.w);
        }
    }
    __syncthreads();
    for (int idx = tid; idx < 16384; idx += 256) buf[idx] = w1[idx];
    __syncthreads();
#pragma unroll
    for (int rr = 0; rr < 2; rr++)
#pragma unroll
        for (int c = 0; c < 4; c++) a[rr][c] = 0.0f;
    for (int k = 0; k < 128; k++) {
        float4 wb = *reinterpret_cast<const float4*>(buf + k * 128 + hg * 4);
        float y0 = xf[(rg * 2) * 128 + k], y1 = xf[(rg * 2 + 1) * 128 + k];
        a[0][0] += y0 * wb.x; a[0][1] += y0 * wb.y; a[0][2] += y0 * wb.z; a[0][3] += y0 * wb.w;
        a[1][0] += y1 * wb.x; a[1][1] += y1 * wb.y; a[1][2] += y1 * wb.z; a[1][3] += y1 * wb.w;
    }
    __syncthreads();
    {
        float4 bb = *reinterpret_cast<const float4*>(b1 + hg * 4);
#pragma unroll
        for (int rr = 0; rr < 2; rr++)
            *reinterpret_cast<float4*>(sy + (rg * 2 + rr) * 128 + hg * 4) =
                make_float4(sspf(a[rr][0] + bb.x), sspf(a[rr][1] + bb.y),
                            sspf(a[rr][2] + bb.z), sspf(a[rr][3] + bb.w));
    }
    __syncthreads();
    {
        int row = tid >> 4, seg = tid & 15;
        float s = 0.0f;
#pragma unroll
        for (int t = 0; t < 8; t++)
            s += sy[row * 128 + seg * 8 + t] * w2s[seg * 8 + t];
        part[tid] = s;
    }
    __syncthreads();
    if (tid < 16) {
        float s = 0.0f;
#pragma unroll
        for (int q = 0; q < 16; q++) s += part[tid * 16 + q];
        out[r0 + tid] = s + b2[0];
    }
}

extern "C" void kernel_launch(void* const* d_in, const int* in_sizes, int n_in,
                              void* d_out, int out_size)
{
    const int*   z       = (const int*)  d_in[0];
    const float* r       = (const float*)d_in[1];
    const float* emb     = (const float*)d_in[2];
    const float* w_in2f  = (const float*)d_in[3];
    const float* w_f1    = (const float*)d_in[4];
    const float* b_f1    = (const float*)d_in[5];
    const float* w_f2    = (const float*)d_in[6];
    const float* b_f2    = (const float*)d_in[7];
    const float* w_f2out = (const float*)d_in[8];
    const float* b_f2out = (const float*)d_in[9];
    const float* w_out   = (const float*)d_in[10];
    const float* b_out   = (const float*)d_in[11];
    const float* w_aw1   = (const float*)d_in[12];
    const float* b_aw1   = (const float*)d_in[13];
    const float* w_aw2   = (const float*)d_in[14];
    const float* b_aw2   = (const float*)d_in[15];
    float* out = (float*)d_out;

    cudaFuncSetAttribute(k_setup, cudaFuncAttributeMaxDynamicSharedMemorySize, 73728);
    cudaFuncSetAttribute(k_iter,  cudaFuncAttributeMaxDynamicSharedMemorySize, 53248);
    cudaFuncSetAttribute(k_ro,    cudaFuncAttributeMaxDynamicSharedMemorySize, 86016);

    k_table<<<512, 128>>>(w_f1, b_f1, w_f2, b_f2);
    k_pack<<<16384, 256>>>();
    k_setup<<<265, 256, 73728>>>(z, emb, w_in2f, w_out, b_out);
    k_prep<<<64, 256>>>(w_f2out);
    for (int it = 0; it < 3; it++)
        k_iter<<<dim3(8, 32), 512, 53248>>>(r, b_f2out, it & 1);
    k_ro<<<256, 256, 86016>>>(w_out, b_out, w_aw1, b_aw1, w_aw2, b_aw2, out);
}